// round 14
// baseline (speedup 1.0000x reference)
#include <cuda_runtime.h>
#include <cuda_fp16.h>
#include <math.h>
#include <float.h>
#include <stdint.h>

#define B_   8
#define V_   4
#define N_   16384
#define CP_  256
#define BV_  (B_*V_)            // 32
#define TM_  128                // points per tile
#define NT_  (N_*BV_/TM_)       // 4096 tiles
#define GRIDP 148               // persistent grid
#define A_STR 528               // padded row stride bytes (256 fp16 + 16 pad)
#define A_IMG    67584          // 128*528
#define OFF_RB   67584          // resident W2 after A buffer (kG1)
#define RB_BYTES 135168         // 256*528
#define DYN_SMEM (OFF_RB + RB_BYTES)   // 202752 (kG1)
#define DYN_SMEM2 (2*A_IMG)            // 135168 (kG2: two A buffers)

// ---------------- device scratch (static; no allocations) -------------------
__device__ float d_center[BV_*3];
__device__ float d_invdiam[BV_];
__device__ float d_stat1[14];
__device__ __align__(16) float d_gmax[BV_*CP_];
__device__ __align__(16) float d_gpart[BV_*CP_];
__device__ float d_mw[BV_*N_];
__device__ float d_denom[BV_];
__device__ __align__(16) unsigned char d_localA[(size_t)NT_*A_IMG];   // 277MB
__device__ __align__(16) uint32_t d_z[(size_t)BV_*N_*128];            // 268MB
__device__ __align__(16) unsigned char d_W2f[CP_*CP_*2];  // fp16 [n][k]
__device__ __align__(16) uint32_t d_W3frag[16*16*32*4];   // W3top fragment-order fp16 (128KB)

// ---------------- helpers ---------------------------------------------------
__device__ __forceinline__ uint32_t sm2u(const void* p) {
    uint32_t a;
    asm("{ .reg .u64 t; cvta.to.shared.u64 t, %1; cvt.u32.u64 %0, t; }"
        : "=r"(a) : "l"(p));
    return a;
}
#define LDSM4(r, addr) \
    asm volatile("ldmatrix.sync.aligned.m8n8.x4.shared.b16 {%0,%1,%2,%3}, [%4];" \
        : "=r"((r)[0]), "=r"((r)[1]), "=r"((r)[2]), "=r"((r)[3]) : "r"(addr))
#define MMAOP(d, a, b0, b1) \
    asm volatile("mma.sync.aligned.m16n8k16.row.col.f32.f16.f16.f32 " \
        "{%0,%1,%2,%3}, {%4,%5,%6,%7}, {%8,%9}, {%0,%1,%2,%3};" \
        : "+f"((d)[0]), "+f"((d)[1]), "+f"((d)[2]), "+f"((d)[3]) \
        : "r"((a)[0]), "r"((a)[1]), "r"((a)[2]), "r"((a)[3]), "r"(b0), "r"(b1))
#define CPA16(dst, src) \
    asm volatile("cp.async.cg.shared.global [%0], [%1], 16;" :: "r"(dst), "l"(src))
#define CPCOMMIT() asm volatile("cp.async.commit_group;" ::: "memory")
#define CPWAIT0()  asm volatile("cp.async.wait_group 0;" ::: "memory")
#define CPWAIT1()  asm volatile("cp.async.wait_group 1;" ::: "memory")

static __device__ __forceinline__ uint32_t pack2h(float v0, float v1) {
    __half h0 = __float2half_rn(v0);
    __half h1 = __float2half_rn(v1);
    return (uint32_t)__half_as_ushort(h0) | ((uint32_t)__half_as_ushort(h1) << 16);
}
__device__ __forceinline__ void atomicMaxFloat(float* addr, float val) {
    if (__float_as_int(val) >= 0) atomicMax((int*)addr, __float_as_int(val));
    else atomicMin((unsigned int*)addr, __float_as_uint(val));
}

__device__ __forceinline__ void loadResidentB(uint32_t su, const unsigned char* g, int tid) {
    for (int i = tid; i < 8192; i += 256) {
        int row = i >> 5, q = i & 31;
        CPA16(su + OFF_RB + (uint32_t)row*A_STR + q*16, g + (size_t)i*16);
    }
}

// ML1: K=256, M=128, W2 resident in smem, zero syncs
#define MAINLOOP_R(ab) \
    _Pragma("unroll 1") \
    for (int ch = 0; ch < 8; ch++) { \
        _Pragma("unroll") \
        for (int kb = 0; kb < 2; kb++) { \
            uint32_t kA = (uint32_t)(ch*64 + kb*32); \
            uint32_t a0[4], a1[4], a2[4], a3[4]; \
            LDSM4(a0, (ab) + aoff0 + kA); \
            LDSM4(a1, (ab) + aoff0 + 16896u + kA); \
            LDSM4(a2, (ab) + aoff0 + 33792u + kA); \
            LDSM4(a3, (ab) + aoff0 + 50688u + kA); \
            _Pragma("unroll") \
            for (int nt = 0; nt < 4; nt++) { \
                uint32_t bh[4]; \
                LDSM4(bh, su + OFF_RB + boff + (uint32_t)(nt*16*A_STR) + kA); \
                MMAOP(dS[0][2*nt],   a0, bh[0], bh[1]); \
                MMAOP(dS[0][2*nt+1], a0, bh[2], bh[3]); \
                MMAOP(dS[1][2*nt],   a1, bh[0], bh[1]); \
                MMAOP(dS[1][2*nt+1], a1, bh[2], bh[3]); \
                MMAOP(dS[2][2*nt],   a2, bh[0], bh[1]); \
                MMAOP(dS[2][2*nt+1], a2, bh[2], bh[3]); \
                MMAOP(dS[3][2*nt],   a3, bh[0], bh[1]); \
                MMAOP(dS[3][2*nt+1], a3, bh[2], bh[3]); \
            } \
        } \
    }

// ---------------- kP: W2 -> fp16 [n][k] -------------------------------------
__global__ void __launch_bounds__(256) kP(const float* __restrict__ W2) {
    int k = blockIdx.x;
    int n = threadIdx.x;
    size_t pos = ((size_t)n*CP_ + k)*2;
    *(unsigned short*)(d_W2f + pos) = __half_as_ushort(__float2half_rn(W2[k*CP_ + n]));
}

// ---------------- kW2: pack W3top into MMA B-fragment order -----------------
// frag for (ch, nstrip, lane l, reg j):
//   n = nstrip*16 + (l>>2) + (j>>1)*8 ; k0 = ch*16 + (j&1)*8 + (l&3)*2
__global__ void __launch_bounds__(128) kW2(const float* __restrict__ W3) {
    int blk = blockIdx.x;          // ch*16 + nstrip
    int ch = blk >> 4, nstrip = blk & 15;
    int tid = threadIdx.x;
    int l = tid >> 2, j = tid & 3;
    int n  = nstrip*16 + (l >> 2) + (j >> 1)*8;
    int k0 = ch*16 + (j & 1)*8 + (l & 3)*2;
    float v0 = W3[(size_t)k0*CP_ + n];
    float v1 = W3[(size_t)(k0+1)*CP_ + n];
    d_W3frag[((size_t)blk*32 + l)*4 + j] = pack2h(v0, v1);
}

// ---------------- kS: analytic LN1 stats aggregates -------------------------
__global__ void __launch_bounds__(256) kS(const float* __restrict__ W1,
                                          const float* __restrict__ b1) {
    __shared__ float sm[14][256];
    int c = threadIdx.x;
    float b = b1[c], w0 = W1[c], w1 = W1[CP_+c], w2 = W1[2*CP_+c];
    sm[0][c]=b;      sm[1][c]=b*b;
    sm[2][c]=w0;     sm[3][c]=w1;     sm[4][c]=w2;
    sm[5][c]=b*w0;   sm[6][c]=b*w1;   sm[7][c]=b*w2;
    sm[8][c]=w0*w0;  sm[9][c]=w0*w1;  sm[10][c]=w0*w2;
    sm[11][c]=w1*w1; sm[12][c]=w1*w2; sm[13][c]=w2*w2;
    __syncthreads();
    for (int s = 128; s > 0; s >>= 1) {
        if (c < s) {
            #pragma unroll
            for (int q = 0; q < 14; q++) sm[q][c] += sm[q][c+s];
        }
        __syncthreads();
    }
    if (c < 14) d_stat1[c] = sm[c][0];
}

// ---------------- kA: per-(b,v) stats + init --------------------------------
__global__ void __launch_bounds__(256) kA(const float* __restrict__ xyz,
                                          const float* __restrict__ masks) {
    int bv = blockIdx.x;
    int b  = bv >> 2;
    int tid = threadIdx.x;

    float s0=0.f, s1=0.f, s2=0.f, cnt=0.f;
    float mx0=-FLT_MAX, mx1=-FLT_MAX, mx2=-FLT_MAX;
    float mn0= FLT_MAX, mn1= FLT_MAX, mn2= FLT_MAX;

    const float* mrow = masks + (size_t)bv*N_;
    const float* x0r  = xyz + (size_t)(b*3+0)*N_;
    const float* x1r  = xyz + (size_t)(b*3+1)*N_;
    const float* x2r  = xyz + (size_t)(b*3+2)*N_;

    for (int n = tid; n < N_; n += 256) {
        float m = mrow[n];
        float a = x0r[n]*m, c = x1r[n]*m, e = x2r[n]*m;
        s0 += a; s1 += c; s2 += e; cnt += m;
        mx0 = fmaxf(mx0,a); mx1 = fmaxf(mx1,c); mx2 = fmaxf(mx2,e);
        mn0 = fminf(mn0,a); mn1 = fminf(mn1,c); mn2 = fminf(mn2,e);
    }
    __shared__ float rs[4][256];
    __shared__ float rx[3][256];
    __shared__ float rn[3][256];
    rs[0][tid]=s0; rs[1][tid]=s1; rs[2][tid]=s2; rs[3][tid]=cnt;
    rx[0][tid]=mx0; rx[1][tid]=mx1; rx[2][tid]=mx2;
    rn[0][tid]=mn0; rn[1][tid]=mn1; rn[2][tid]=mn2;
    __syncthreads();
    for (int s = 128; s > 0; s >>= 1) {
        if (tid < s) {
            #pragma unroll
            for (int q = 0; q < 4; q++) rs[q][tid] += rs[q][tid+s];
            #pragma unroll
            for (int q = 0; q < 3; q++) {
                rx[q][tid] = fmaxf(rx[q][tid], rx[q][tid+s]);
                rn[q][tid] = fminf(rn[q][tid], rn[q][tid+s]);
            }
        }
        __syncthreads();
    }
    if (tid == 0) {
        float valid = fmaxf(rs[3][0], 1.f);
        d_center[bv*3+0] = rs[0][0]/valid;
        d_center[bv*3+1] = rs[1][0]/valid;
        d_center[bv*3+2] = rs[2][0]/valid;
        float diam = fmaxf(fmaxf(rx[0][0]-rn[0][0], rx[1][0]-rn[1][0]),
                           rx[2][0]-rn[2][0]);
        if (diam == 0.f) diam = 1.f;
        d_invdiam[bv] = 1.f/diam;
        d_denom[bv]   = 0.f;
    }
    d_gmax[bv*CP_ + tid] = -FLT_MAX;
}

// ---- kG1 (persistent, M=128): stage1 -> GEMM(W2) -> reg-LN2 -> local+gmax --
__global__ void __launch_bounds__(256) kG1(const float* __restrict__ xyz,
    const float* __restrict__ W1, const float* __restrict__ b1,
    const float* __restrict__ g1, const float* __restrict__ be1,
    const float* __restrict__ b2, const float* __restrict__ g2,
    const float* __restrict__ be2)
{
    extern __shared__ unsigned char ds[];
    __shared__ float w1s[3*CP_];
    __shared__ float b1s[CP_], g1s[CP_], e1s[CP_], b2s[CP_], g2s[CP_], e2s[CP_];
    __shared__ float srS[TM_][4], srQ[TM_][4];
    __shared__ float sMean[TM_], sRstd[TM_];
    __shared__ float scx[2][CP_];
    __shared__ float sCen[3*BV_], sInv[BV_], sSt[14];

    int tid = threadIdx.x, lane = tid & 31, wid = tid >> 5;
    uint32_t su = sm2u(ds);

    loadResidentB(su, d_W2f, tid); CPCOMMIT();

    for (int i = tid; i < 3*CP_; i += 256) w1s[i] = W1[i];
    b1s[tid]=b1[tid]; g1s[tid]=g1[tid]; e1s[tid]=be1[tid];
    b2s[tid]=b2[tid]; g2s[tid]=g2[tid]; e2s[tid]=be2[tid];
    if (tid < 3*BV_) sCen[tid] = d_center[tid];
    if (tid < BV_)   sInv[tid] = d_invdiam[tid];
    if (tid < 14)    sSt[tid]  = d_stat1[tid];
    CPWAIT0();
    __syncthreads();

    int p = tid >> 1, half = tid & 1, c0 = half*128;
    int mt0 = (wid >> 2) * 16;
    int nb  = (wid & 3) * 64;
    uint32_t aoff0 = (uint32_t)(mt0 + (lane&7) + ((lane>>3)&1)*8)*A_STR + (lane>>4)*16;
    uint32_t boff  = (uint32_t)(nb + (lane&7) + (lane>>4)*8)*A_STR + ((lane>>3)&1)*16;
    int r = lane >> 2, q2 = (lane & 3)*2;

    for (int tile = blockIdx.x; tile < NT_; tile += GRIDP) {
        int bv = tile >> 7;
        int b  = bv >> 2;

        int n = (tile & 127) * TM_ + p;
        float idm = sInv[bv];
        float x0 = (xyz[(size_t)(b*3+0)*N_ + n] - sCen[bv*3+0]) * idm;
        float x1 = (xyz[(size_t)(b*3+1)*N_ + n] - sCen[bv*3+1]) * idm;
        float x2 = (xyz[(size_t)(b*3+2)*N_ + n] - sCen[bv*3+2]) * idm;
        float S  = sSt[0] + x0*sSt[2] + x1*sSt[3] + x2*sSt[4];
        float E2 = sSt[1] + 2.f*(x0*sSt[5] + x1*sSt[6] + x2*sSt[7])
                 + x0*x0*sSt[8]  + 2.f*x0*x1*sSt[9] + 2.f*x0*x2*sSt[10]
                 + x1*x1*sSt[11] + 2.f*x1*x2*sSt[12] + x2*x2*sSt[13];
        float mean = S * (1.f/CP_);
        float rstd = rsqrtf(E2*(1.f/CP_) - mean*mean + 1e-5f);
        #pragma unroll 8
        for (int i = 0; i < 64; i++) {
            int c = c0 + 2*i;
            float y0 = b1s[c]   + x0*w1s[c]   + x1*w1s[CP_+c]   + x2*w1s[2*CP_+c];
            float y1 = b1s[c+1] + x0*w1s[c+1] + x1*w1s[CP_+c+1] + x2*w1s[2*CP_+c+1];
            y0 = fmaxf((y0-mean)*rstd*g1s[c]   + e1s[c],   0.f);
            y1 = fmaxf((y1-mean)*rstd*g1s[c+1] + e1s[c+1], 0.f);
            *(uint32_t*)(ds + (size_t)p*A_STR + c*2) = pack2h(y0, y1);
        }
        __syncthreads();

        float dS[4][8][4] = {};
        MAINLOOP_R(su)

        float rsm[4][2] = {}, rqm[4][2] = {};
        #pragma unroll
        for (int s = 0; s < 4; s++) {
            #pragma unroll
            for (int f = 0; f < 8; f++) {
                int c = nb + f*8 + q2;
                float bb0 = b2s[c], bb1 = b2s[c+1], v;
                v = dS[s][f][0]+bb0; rsm[s][0]+=v; rqm[s][0]+=v*v;
                v = dS[s][f][1]+bb1; rsm[s][0]+=v; rqm[s][0]+=v*v;
                v = dS[s][f][2]+bb0; rsm[s][1]+=v; rqm[s][1]+=v*v;
                v = dS[s][f][3]+bb1; rsm[s][1]+=v; rqm[s][1]+=v*v;
            }
        }
        #pragma unroll
        for (int s = 0; s < 4; s++) {
            #pragma unroll
            for (int h = 0; h < 2; h++) {
                rsm[s][h] += __shfl_xor_sync(~0u, rsm[s][h], 1);
                rsm[s][h] += __shfl_xor_sync(~0u, rsm[s][h], 2);
                rqm[s][h] += __shfl_xor_sync(~0u, rqm[s][h], 1);
                rqm[s][h] += __shfl_xor_sync(~0u, rqm[s][h], 2);
            }
        }
        if ((lane & 3) == 0) {
            int w4 = wid & 3;
            #pragma unroll
            for (int s = 0; s < 4; s++) {
                #pragma unroll
                for (int h = 0; h < 2; h++) {
                    int row = mt0 + s*32 + h*8 + r;
                    srS[row][w4] = rsm[s][h];
                    srQ[row][w4] = rqm[s][h];
                }
            }
        }
        __syncthreads();
        if (tid < TM_) {
            float Ss = srS[tid][0]+srS[tid][1]+srS[tid][2]+srS[tid][3];
            float Qs = srQ[tid][0]+srQ[tid][1]+srQ[tid][2]+srQ[tid][3];
            float mn = Ss * (1.f/CP_);
            sMean[tid] = mn;
            sRstd[tid] = rsqrtf(Qs*(1.f/CP_) - mn*mn + 1e-5f);
        }
        __syncthreads();

        {
            unsigned char* lw = d_localA + (size_t)tile*A_IMG;
            float cm[16];
            #pragma unroll
            for (int i = 0; i < 16; i++) cm[i] = -FLT_MAX;
            #pragma unroll
            for (int s = 0; s < 4; s++) {
                int row0 = mt0 + s*32 + r, row1 = row0 + 8;
                float m0 = sMean[row0], rr0 = sRstd[row0];
                float m1 = sMean[row1], rr1 = sRstd[row1];
                #pragma unroll
                for (int f = 0; f < 8; f++) {
                    int c = nb + f*8 + q2;
                    float bb0=b2s[c], bb1=b2s[c+1], g0=g2s[c], g1=g2s[c+1];
                    float e0=e2s[c], e1=e2s[c+1];
                    float v00 = (dS[s][f][0]+bb0-m0)*rr0*g0+e0;
                    float v01 = (dS[s][f][1]+bb1-m0)*rr0*g1+e1;
                    float v10 = (dS[s][f][2]+bb0-m1)*rr1*g0+e0;
                    float v11 = (dS[s][f][3]+bb1-m1)*rr1*g1+e1;
                    *(uint32_t*)(lw + (size_t)row0*A_STR + c*2) = pack2h(v00, v01);
                    *(uint32_t*)(lw + (size_t)row1*A_STR + c*2) = pack2h(v10, v11);
                    cm[2*f]   = fmaxf(cm[2*f],   fmaxf(v00, v10));
                    cm[2*f+1] = fmaxf(cm[2*f+1], fmaxf(v01, v11));
                }
            }
            #pragma unroll
            for (int i = 0; i < 16; i++) {
                cm[i] = fmaxf(cm[i], __shfl_xor_sync(~0u, cm[i], 4));
                cm[i] = fmaxf(cm[i], __shfl_xor_sync(~0u, cm[i], 8));
                cm[i] = fmaxf(cm[i], __shfl_xor_sync(~0u, cm[i], 16));
            }
            if ((lane >> 2) == 0) {
                int grp = wid >> 2;
                #pragma unroll
                for (int f = 0; f < 8; f++) {
                    int c = nb + f*8 + q2;
                    scx[grp][c]   = cm[2*f];
                    scx[grp][c+1] = cm[2*f+1];
                }
            }
        }
        __syncthreads();
        atomicMaxFloat(&d_gmax[bv*CP_ + tid], fmaxf(scx[0][tid], scx[1][tid]));
        __syncthreads();
    }
}

// ---- kG2 (persistent): local -> GEMM(W3top via LDG frags) -> z -------------
// A double-buffered in smem; B fragments straight from L2-hot 128KB table.
__global__ void __launch_bounds__(256) kG2() {
    extern __shared__ unsigned char ds[];
    int tid = threadIdx.x, lane = tid & 31, wid = tid >> 5;
    uint32_t su = sm2u(ds);

    {   // prefetch A for first two tiles
        int t0 = blockIdx.x;
        if (t0 < NT_) {
            const unsigned char* src = d_localA + (size_t)t0*A_IMG;
            for (int i = tid; i < A_IMG/16; i += 256)
                CPA16(su + (uint32_t)i*16, src + (size_t)i*16);
        }
        CPCOMMIT();
        int t1 = blockIdx.x + GRIDP;
        if (t1 < NT_) {
            const unsigned char* src = d_localA + (size_t)t1*A_IMG;
            for (int i = tid; i < A_IMG/16; i += 256)
                CPA16(su + A_IMG + (uint32_t)i*16, src + (size_t)i*16);
        }
        CPCOMMIT();
    }

    int mt0 = (wid >> 2) * 16;
    int nb  = (wid & 3) * 64;
    int nsb = (wid & 3) * 4;
    uint32_t aoff0 = (uint32_t)(mt0 + (lane&7) + ((lane>>3)&1)*8)*A_STR + (lane>>4)*16;
    int r = lane >> 2, q2 = (lane & 3)*2;
    const uint4* wf = (const uint4*)d_W3frag;

    int it = 0;
    for (int tile = blockIdx.x; tile < NT_; tile += GRIDP, it++) {
        CPWAIT1();
        __syncthreads();
        uint32_t ab = su + (uint32_t)(it & 1)*A_IMG;

        float dS[4][8][4] = {};
        uint4 bcur[4];
        #pragma unroll
        for (int nt = 0; nt < 4; nt++)
            bcur[nt] = wf[(size_t)((nsb + nt)*32 + lane)];
        #pragma unroll 1
        for (int ch = 0; ch < 16; ch++) {
            uint4 bnext[4];
            if (ch < 15) {
                #pragma unroll
                for (int nt = 0; nt < 4; nt++)
                    bnext[nt] = wf[(size_t)(((ch+1)*16 + nsb + nt)*32 + lane)];
            }
            uint32_t kA = (uint32_t)(ch*32);
            uint32_t a0[4], a1[4], a2[4], a3[4];
            LDSM4(a0, ab + aoff0 + kA);
            LDSM4(a1, ab + aoff0 + 16896u + kA);
            LDSM4(a2, ab + aoff0 + 33792u + kA);
            LDSM4(a3, ab + aoff0 + 50688u + kA);
            #pragma unroll
            for (int nt = 0; nt < 4; nt++) {
                uint32_t bh[4] = {bcur[nt].x, bcur[nt].y, bcur[nt].z, bcur[nt].w};
                MMAOP(dS[0][2*nt],   a0, bh[0], bh[1]);
                MMAOP(dS[0][2*nt+1], a0, bh[2], bh[3]);
                MMAOP(dS[1][2*nt],   a1, bh[0], bh[1]);
                MMAOP(dS[1][2*nt+1], a1, bh[2], bh[3]);
                MMAOP(dS[2][2*nt],   a2, bh[0], bh[1]);
                MMAOP(dS[2][2*nt+1], a2, bh[2], bh[3]);
                MMAOP(dS[3][2*nt],   a3, bh[0], bh[1]);
                MMAOP(dS[3][2*nt+1], a3, bh[2], bh[3]);
            }
            if (ch < 15) {
                #pragma unroll
                for (int nt = 0; nt < 4; nt++) bcur[nt] = bnext[nt];
            }
        }
        __syncthreads();   // all A reads done before refilling this buffer

        {   // refill current buffer with tile+2*GRIDP (overlaps epilogue)
            int nxt = tile + 2*GRIDP;
            if (nxt < NT_) {
                const unsigned char* src = d_localA + (size_t)nxt*A_IMG;
                for (int i = tid; i < A_IMG/16; i += 256)
                    CPA16(ab + (uint32_t)i*16, src + (size_t)i*16);
            }
            CPCOMMIT();
        }

        uint32_t* zb = d_z + (size_t)tile*TM_*128;
        #pragma unroll
        for (int s = 0; s < 4; s++) {
            int row0 = mt0 + s*32 + r, row1 = row0 + 8;
            #pragma unroll
            for (int f = 0; f < 8; f++) {
                int cw = (nb + f*8 + q2) >> 1;
                zb[(size_t)row0*128 + cw] = pack2h(dS[s][f][0], dS[s][f][1]);
                zb[(size_t)row1*128 + cw] = pack2h(dS[s][f][2], dS[s][f][3]);
            }
        }
    }
}

// ---------------- kC: gpart = global_xyz @ W3[256:512] + b3 -----------------
__global__ void __launch_bounds__(256) kC(const float* __restrict__ W3,
                                          const float* __restrict__ b3) {
    int bv = blockIdx.x;
    int c  = threadIdx.x;
    __shared__ float sg[CP_];
    __shared__ float ws[32*CP_];
    sg[c] = d_gmax[bv*CP_ + c];
    float acc = b3[c];
    for (int ko = 0; ko < 8; ko++) {
        __syncthreads();
        const float4* src = (const float4*)(W3 + (size_t)(256 + ko*32)*CP_);
        for (int i = c; i < 32*CP_/4; i += 256) ((float4*)ws)[i] = src[i];
        __syncthreads();
        #pragma unroll 8
        for (int kk = 0; kk < 32; kk++)
            acc += sg[ko*32+kk] * ws[kk*CP_ + c];
    }
    d_gpart[bv*CP_ + c] = acc;
}

// ---------------- kD: streaming LN3 + ReLU + W4 -> weights ------------------
__global__ void __launch_bounds__(256) kD(const float* __restrict__ masks,
    const float* __restrict__ g3, const float* __restrict__ be3,
    const float* __restrict__ W4)
{
    __shared__ float sGp[CP_], sG3[CP_], sE3[CP_], sW4[CP_];
    int blk = blockIdx.x;
    int bv = blk >> 5;
    int pbase = (blk & 31) * 512;
    int tid = threadIdx.x, lane = tid & 31, wid = tid >> 5;

    sGp[tid] = d_gpart[bv*CP_ + tid];
    sG3[tid] = g3[tid]; sE3[tid] = be3[tid]; sW4[tid] = W4[tid];
    __syncthreads();

    int cbase = lane*8;
    float gp[8], gg[8], ee[8], ww[8];
    #pragma unroll
    for (int j = 0; j < 8; j++) {
        gp[j]=sGp[cbase+j]; gg[j]=sG3[cbase+j]; ee[j]=sE3[cbase+j]; ww[j]=sW4[cbase+j];
    }

    float dacc = 0.f;
    for (int pp = wid; pp < 512; pp += 8) {
        int n = pbase + pp;
        size_t pt = (size_t)bv*N_ + n;
        uint4 w = *(const uint4*)(d_z + pt*128 + lane*4);
        uint32_t ws4[4] = {w.x, w.y, w.z, w.w};
        float v[8];
        #pragma unroll
        for (int j = 0; j < 4; j++) {
            __half2 h2 = *reinterpret_cast<__half2*>(&ws4[j]);
            float2 f = __half22float2(h2);
            v[2*j]   = f.x + gp[2*j];
            v[2*j+1] = f.y + gp[2*j+1];
        }
        float s = 0.f, q = 0.f;
        #pragma unroll
        for (int j = 0; j < 8; j++) { s += v[j]; q += v[j]*v[j]; }
        #pragma unroll
        for (int o = 16; o > 0; o >>= 1) {
            s += __shfl_xor_sync(~0u, s, o);
            q += __shfl_xor_sync(~0u, q, o);
        }
        float mean = s * (1.f/CP_);
        float rstd = rsqrtf(q*(1.f/CP_) - mean*mean + 1e-5f);
        float dot = 0.f;
        #pragma unroll
        for (int j = 0; j < 8; j++)
            dot += fmaxf((v[j]-mean)*rstd*gg[j] + ee[j], 0.f) * ww[j];
        #pragma unroll
        for (int o = 16; o > 0; o >>= 1) dot += __shfl_xor_sync(~0u, dot, o);
        if (lane == 0) {
            float m = masks[pt];
            float wgt = 2.f * m / (1.f + expf(-dot));
            d_mw[pt] = wgt;
            dacc += wgt;
        }
    }
    if (lane == 0) atomicAdd(&d_denom[bv], dacc);
}

// ---------------- kE: weighted pooling + epilogue ---------------------------
__global__ void __launch_bounds__(256) kE(const float* __restrict__ feats,
                                          float* __restrict__ out) {
    int blk = blockIdx.x;
    int b = blk >> 8;
    int c = blk & 255;
    int tid = threadIdx.x;

    const float* f   = feats + (size_t)(b*CP_ + c)*N_;
    const float* mw0 = d_mw + (size_t)(b*4+0)*N_;
    const float* mw1 = d_mw + (size_t)(b*4+1)*N_;
    const float* mw2 = d_mw + (size_t)(b*4+2)*N_;
    const float* mw3 = d_mw + (size_t)(b*4+3)*N_;

    float a0=0.f, a1=0.f, a2=0.f, a3=0.f;
    for (int n = tid; n < N_; n += 256) {
        float fv = f[n];
        a0 += fv*mw0[n]; a1 += fv*mw1[n]; a2 += fv*mw2[n]; a3 += fv*mw3[n];
    }
    #pragma unroll
    for (int o = 16; o > 0; o >>= 1) {
        a0 += __shfl_xor_sync(0xffffffffu, a0, o);
        a1 += __shfl_xor_sync(0xffffffffu, a1, o);
        a2 += __shfl_xor_sync(0xffffffffu, a2, o);
        a3 += __shfl_xor_sync(0xffffffffu, a3, o);
    }
    __shared__ float sr[4][8];
    int lane = tid & 31, warp = tid >> 5;
    if (lane == 0) { sr[0][warp]=a0; sr[1][warp]=a1; sr[2][warp]=a2; sr[3][warp]=a3; }
    __syncthreads();
    if (tid < 4) {
        float ps = 0.f;
        #pragma unroll
        for (int w = 0; w < 8; w++) ps += sr[tid][w];
        int bvv = b*4 + tid;
        float den = fmaxf(d_denom[bvv], 1e-8f);
        out[(size_t)bvv*CP_ + c] = ps/den + d_gmax[bvv*CP_ + c];
    }
}

// ---------------- launch ----------------------------------------------------
extern "C" void kernel_launch(void* const* d_in, const int* in_sizes, int n_in,
                              void* d_out, int out_size) {
    const float* xyz = (const float*)d_in[0];
    const float* pf  = (const float*)d_in[1];
    const float* pm  = (const float*)d_in[2];
    const float* W1  = (const float*)d_in[3];
    const float* b1  = (const float*)d_in[4];
    const float* g1  = (const float*)d_in[5];
    const float* be1 = (const float*)d_in[6];
    const float* W2  = (const float*)d_in[7];
    const float* b2  = (const float*)d_in[8];
    const float* g2  = (const float*)d_in[9];
    const float* be2 = (const float*)d_in[10];
    const float* W3  = (const float*)d_in[11];
    const float* b3  = (const float*)d_in[12];
    const float* g3  = (const float*)d_in[13];
    const float* be3 = (const float*)d_in[14];
    const float* W4  = (const float*)d_in[15];
    float* out = (float*)d_out;

    static int configured = 0;
    if (!configured) {
        cudaFuncSetAttribute(kG1, cudaFuncAttributeMaxDynamicSharedMemorySize, DYN_SMEM);
        cudaFuncSetAttribute(kG2, cudaFuncAttributeMaxDynamicSharedMemorySize, DYN_SMEM2);
        configured = 1;
    }

    kP<<<CP_, 256>>>(W2);
    kW2<<<256, 128>>>(W3);
    kS<<<1, 256>>>(W1, b1);
    kA<<<BV_, 256>>>(xyz, pm);
    kG1<<<GRIDP, 256, DYN_SMEM>>>(xyz, W1, b1, g1, be1, b2, g2, be2);
    kC<<<BV_, 256>>>(W3, b3);
    kG2<<<GRIDP, 256, DYN_SMEM2>>>();
    kD<<<1024, 256>>>(pm, g3, be3, W4);
    kE<<<B_*CP_, 256>>>(pf, out);
}

// round 15
// speedup vs baseline: 1.0626x; 1.0626x over previous
#include <cuda_runtime.h>
#include <cuda_fp16.h>
#include <math.h>
#include <float.h>
#include <stdint.h>

#define B_   8
#define V_   4
#define N_   16384
#define CP_  256
#define BV_  (B_*V_)            // 32
#define TM_  128                // points per tile
#define NT_  (N_*BV_/TM_)       // 4096 tiles
#define GRIDP 148               // persistent grid
#define A_STR 528               // padded row stride bytes (256 fp16 + 16 pad)
#define A_IMG    67584          // 128*528
#define OFF_RB   67584          // resident weights after A buffer
#define RB_BYTES 135168         // 256*528
#define DYN_SMEM (OFF_RB + RB_BYTES)   // 202752

// ---------------- device scratch (static; no allocations) -------------------
__device__ float d_stat1[14];
__device__ float d_part[BV_*8*10];   // per-slice partials: s0 s1 s2 cnt mx0..2 mn0..2
__device__ __align__(16) float d_gmax[BV_*CP_];
__device__ __align__(16) float d_gpart[BV_*CP_];
__device__ float d_mw[BV_*N_];
__device__ float d_denom[BV_];
__device__ __align__(16) unsigned char d_localA[(size_t)NT_*A_IMG];   // 277MB
__device__ __align__(16) uint32_t d_z[(size_t)BV_*N_*128];            // 268MB
__device__ __align__(16) unsigned char d_W2f[CP_*CP_*2];  // fp16 [n][k]
__device__ __align__(16) unsigned char d_W3f[CP_*CP_*2];  // fp16 [n][k] (W3 top)

// ---------------- helpers ---------------------------------------------------
__device__ __forceinline__ uint32_t sm2u(const void* p) {
    uint32_t a;
    asm("{ .reg .u64 t; cvta.to.shared.u64 t, %1; cvt.u32.u64 %0, t; }"
        : "=r"(a) : "l"(p));
    return a;
}
#define LDSM4(r, addr) \
    asm volatile("ldmatrix.sync.aligned.m8n8.x4.shared.b16 {%0,%1,%2,%3}, [%4];" \
        : "=r"((r)[0]), "=r"((r)[1]), "=r"((r)[2]), "=r"((r)[3]) : "r"(addr))
#define MMAOP(d, a, b0, b1) \
    asm volatile("mma.sync.aligned.m16n8k16.row.col.f32.f16.f16.f32 " \
        "{%0,%1,%2,%3}, {%4,%5,%6,%7}, {%8,%9}, {%0,%1,%2,%3};" \
        : "+f"((d)[0]), "+f"((d)[1]), "+f"((d)[2]), "+f"((d)[3]) \
        : "r"((a)[0]), "r"((a)[1]), "r"((a)[2]), "r"((a)[3]), "r"(b0), "r"(b1))
#define CPA16(dst, src) \
    asm volatile("cp.async.cg.shared.global [%0], [%1], 16;" :: "r"(dst), "l"(src))
#define CPCOMMIT() asm volatile("cp.async.commit_group;" ::: "memory")
#define CPWAIT0()  asm volatile("cp.async.wait_group 0;" ::: "memory")

static __device__ __forceinline__ uint32_t pack2h(float v0, float v1) {
    __half h0 = __float2half_rn(v0);
    __half h1 = __float2half_rn(v1);
    return (uint32_t)__half_as_ushort(h0) | ((uint32_t)__half_as_ushort(h1) << 16);
}
__device__ __forceinline__ void atomicMaxFloat(float* addr, float val) {
    if (__float_as_int(val) >= 0) atomicMax((int*)addr, __float_as_int(val));
    else atomicMin((unsigned int*)addr, __float_as_uint(val));
}

__device__ __forceinline__ void loadResidentB(uint32_t su, const unsigned char* g, int tid) {
    for (int i = tid; i < 8192; i += 256) {
        int row = i >> 5, q = i & 31;
        CPA16(su + OFF_RB + (uint32_t)row*A_STR + q*16, g + (size_t)i*16);
    }
}

// K=256 mainloop, M=128: 4 m-strips per warp, B resident, zero syncs
#define MAINLOOP_R(ab) \
    _Pragma("unroll 1") \
    for (int ch = 0; ch < 8; ch++) { \
        _Pragma("unroll") \
        for (int kb = 0; kb < 2; kb++) { \
            uint32_t kA = (uint32_t)(ch*64 + kb*32); \
            uint32_t a0[4], a1[4], a2[4], a3[4]; \
            LDSM4(a0, (ab) + aoff0 + kA); \
            LDSM4(a1, (ab) + aoff0 + 16896u + kA); \
            LDSM4(a2, (ab) + aoff0 + 33792u + kA); \
            LDSM4(a3, (ab) + aoff0 + 50688u + kA); \
            _Pragma("unroll") \
            for (int nt = 0; nt < 4; nt++) { \
                uint32_t bh[4]; \
                LDSM4(bh, su + OFF_RB + boff + (uint32_t)(nt*16*A_STR) + kA); \
                MMAOP(dS[0][2*nt],   a0, bh[0], bh[1]); \
                MMAOP(dS[0][2*nt+1], a0, bh[2], bh[3]); \
                MMAOP(dS[1][2*nt],   a1, bh[0], bh[1]); \
                MMAOP(dS[1][2*nt+1], a1, bh[2], bh[3]); \
                MMAOP(dS[2][2*nt],   a2, bh[0], bh[1]); \
                MMAOP(dS[2][2*nt+1], a2, bh[2], bh[3]); \
                MMAOP(dS[3][2*nt],   a3, bh[0], bh[1]); \
                MMAOP(dS[3][2*nt+1], a3, bh[2], bh[3]); \
            } \
        } \
    }

// ---------------- kPre: fused preprocessing ---------------------------------
// blocks 0..255   : weights -> fp16 [n][k]           (k = blk)
// block  256      : LN1 analytic aggregates
// block  257      : init d_gmax / d_denom
// blocks 258..513 : kA partials (bv = (blk-258)>>3, slice = (blk-258)&7)
__global__ void __launch_bounds__(256) kPre(const float* __restrict__ W2,
    const float* __restrict__ W3, const float* __restrict__ W1,
    const float* __restrict__ b1, const float* __restrict__ xyz,
    const float* __restrict__ masks)
{
    int blk = blockIdx.x;
    int tid = threadIdx.x;

    if (blk < 256) {                       // weight conversion
        int k = blk, n = tid;
        size_t pos = ((size_t)n*CP_ + k)*2;
        *(unsigned short*)(d_W2f + pos) = __half_as_ushort(__float2half_rn(W2[k*CP_ + n]));
        *(unsigned short*)(d_W3f + pos) = __half_as_ushort(__float2half_rn(W3[k*CP_ + n]));
        return;
    }
    if (blk == 256) {                      // LN1 aggregates
        __shared__ float sm[14][256];
        int c = tid;
        float b = b1[c], w0 = W1[c], w1 = W1[CP_+c], w2 = W1[2*CP_+c];
        sm[0][c]=b;      sm[1][c]=b*b;
        sm[2][c]=w0;     sm[3][c]=w1;     sm[4][c]=w2;
        sm[5][c]=b*w0;   sm[6][c]=b*w1;   sm[7][c]=b*w2;
        sm[8][c]=w0*w0;  sm[9][c]=w0*w1;  sm[10][c]=w0*w2;
        sm[11][c]=w1*w1; sm[12][c]=w1*w2; sm[13][c]=w2*w2;
        __syncthreads();
        for (int s = 128; s > 0; s >>= 1) {
            if (c < s) {
                #pragma unroll
                for (int q = 0; q < 14; q++) sm[q][c] += sm[q][c+s];
            }
            __syncthreads();
        }
        if (c < 14) d_stat1[c] = sm[c][0];
        return;
    }
    if (blk == 257) {                      // init
        for (int i = tid; i < BV_*CP_; i += 256) d_gmax[i] = -FLT_MAX;
        if (tid < BV_) d_denom[tid] = 0.f;
        return;
    }

    // kA partials
    int blk2 = blk - 258;
    int bv = blk2 >> 3, slice = blk2 & 7;
    int b  = bv >> 2;
    int n0 = slice * (N_/8);               // 2048 points

    float s0=0.f, s1=0.f, s2=0.f, cnt=0.f;
    float mx0=-FLT_MAX, mx1=-FLT_MAX, mx2=-FLT_MAX;
    float mn0= FLT_MAX, mn1= FLT_MAX, mn2= FLT_MAX;
    const float* mrow = masks + (size_t)bv*N_ + n0;
    const float* x0r  = xyz + (size_t)(b*3+0)*N_ + n0;
    const float* x1r  = xyz + (size_t)(b*3+1)*N_ + n0;
    const float* x2r  = xyz + (size_t)(b*3+2)*N_ + n0;
    for (int n = tid; n < N_/8; n += 256) {
        float m = mrow[n];
        float a = x0r[n]*m, c = x1r[n]*m, e = x2r[n]*m;
        s0 += a; s1 += c; s2 += e; cnt += m;
        mx0 = fmaxf(mx0,a); mx1 = fmaxf(mx1,c); mx2 = fmaxf(mx2,e);
        mn0 = fminf(mn0,a); mn1 = fminf(mn1,c); mn2 = fminf(mn2,e);
    }
    __shared__ float rs[10][256];
    rs[0][tid]=s0; rs[1][tid]=s1; rs[2][tid]=s2; rs[3][tid]=cnt;
    rs[4][tid]=mx0; rs[5][tid]=mx1; rs[6][tid]=mx2;
    rs[7][tid]=mn0; rs[8][tid]=mn1; rs[9][tid]=mn2;
    __syncthreads();
    for (int s = 128; s > 0; s >>= 1) {
        if (tid < s) {
            #pragma unroll
            for (int q = 0; q < 4; q++) rs[q][tid] += rs[q][tid+s];
            #pragma unroll
            for (int q = 4; q < 7; q++) rs[q][tid] = fmaxf(rs[q][tid], rs[q][tid+s]);
            #pragma unroll
            for (int q = 7; q < 10; q++) rs[q][tid] = fminf(rs[q][tid], rs[q][tid+s]);
        }
        __syncthreads();
    }
    if (tid < 10) d_part[(size_t)blk2*10 + tid] = rs[tid][0];
}

// ---- kG1 (persistent, M=128): stage1 -> GEMM(W2) -> reg-LN2 -> local+gmax --
__global__ void __launch_bounds__(256) kG1(const float* __restrict__ xyz,
    const float* __restrict__ W1, const float* __restrict__ b1,
    const float* __restrict__ g1, const float* __restrict__ be1,
    const float* __restrict__ b2, const float* __restrict__ g2,
    const float* __restrict__ be2)
{
    extern __shared__ unsigned char ds[];
    __shared__ float w1s[3*CP_];
    __shared__ float b1s[CP_], g1s[CP_], e1s[CP_], b2s[CP_], g2s[CP_], e2s[CP_];
    __shared__ float srS[TM_][4], srQ[TM_][4];
    __shared__ float sMean[TM_], sRstd[TM_];
    __shared__ float scx[2][CP_];
    __shared__ float sCen[3*BV_], sInv[BV_], sSt[14];

    int tid = threadIdx.x, lane = tid & 31, wid = tid >> 5;
    uint32_t su = sm2u(ds);

    loadResidentB(su, d_W2f, tid); CPCOMMIT();

    for (int i = tid; i < 3*CP_; i += 256) w1s[i] = W1[i];
    b1s[tid]=b1[tid]; g1s[tid]=g1[tid]; e1s[tid]=be1[tid];
    b2s[tid]=b2[tid]; g2s[tid]=g2[tid]; e2s[tid]=be2[tid];
    if (tid < BV_) {                       // finalize per-(b,v) stats from partials
        float s0=0.f,s1=0.f,s2=0.f,cnt=0.f;
        float mx0=-FLT_MAX,mx1=-FLT_MAX,mx2=-FLT_MAX;
        float mn0=FLT_MAX,mn1=FLT_MAX,mn2=FLT_MAX;
        #pragma unroll
        for (int sl = 0; sl < 8; sl++) {
            const float* pp = d_part + (size_t)(tid*8+sl)*10;
            s0+=pp[0]; s1+=pp[1]; s2+=pp[2]; cnt+=pp[3];
            mx0=fmaxf(mx0,pp[4]); mx1=fmaxf(mx1,pp[5]); mx2=fmaxf(mx2,pp[6]);
            mn0=fminf(mn0,pp[7]); mn1=fminf(mn1,pp[8]); mn2=fminf(mn2,pp[9]);
        }
        float valid = fmaxf(cnt, 1.f);
        sCen[tid*3+0]=s0/valid; sCen[tid*3+1]=s1/valid; sCen[tid*3+2]=s2/valid;
        float diam = fmaxf(fmaxf(mx0-mn0, mx1-mn1), mx2-mn2);
        if (diam == 0.f) diam = 1.f;
        sInv[tid] = 1.f/diam;
    }
    if (tid < 14) sSt[tid] = d_stat1[tid];
    CPWAIT0();
    __syncthreads();

    int p = tid >> 1, half = tid & 1, c0 = half*128;
    int mt0 = (wid >> 2) * 16;
    int nb  = (wid & 3) * 64;
    uint32_t aoff0 = (uint32_t)(mt0 + (lane&7) + ((lane>>3)&1)*8)*A_STR + (lane>>4)*16;
    uint32_t boff  = (uint32_t)(nb + (lane&7) + (lane>>4)*8)*A_STR + ((lane>>3)&1)*16;
    int r = lane >> 2, q2 = (lane & 3)*2;

    for (int tile = blockIdx.x; tile < NT_; tile += GRIDP) {
        int bv = tile >> 7;
        int b  = bv >> 2;

        int n = (tile & 127) * TM_ + p;
        float idm = sInv[bv];
        float x0 = (xyz[(size_t)(b*3+0)*N_ + n] - sCen[bv*3+0]) * idm;
        float x1 = (xyz[(size_t)(b*3+1)*N_ + n] - sCen[bv*3+1]) * idm;
        float x2 = (xyz[(size_t)(b*3+2)*N_ + n] - sCen[bv*3+2]) * idm;
        float S  = sSt[0] + x0*sSt[2] + x1*sSt[3] + x2*sSt[4];
        float E2 = sSt[1] + 2.f*(x0*sSt[5] + x1*sSt[6] + x2*sSt[7])
                 + x0*x0*sSt[8]  + 2.f*x0*x1*sSt[9] + 2.f*x0*x2*sSt[10]
                 + x1*x1*sSt[11] + 2.f*x1*x2*sSt[12] + x2*x2*sSt[13];
        float mean = S * (1.f/CP_);
        float rstd = rsqrtf(E2*(1.f/CP_) - mean*mean + 1e-5f);
        #pragma unroll 8
        for (int i = 0; i < 64; i++) {
            int c = c0 + 2*i;
            float y0 = b1s[c]   + x0*w1s[c]   + x1*w1s[CP_+c]   + x2*w1s[2*CP_+c];
            float y1 = b1s[c+1] + x0*w1s[c+1] + x1*w1s[CP_+c+1] + x2*w1s[2*CP_+c+1];
            y0 = fmaxf((y0-mean)*rstd*g1s[c]   + e1s[c],   0.f);
            y1 = fmaxf((y1-mean)*rstd*g1s[c+1] + e1s[c+1], 0.f);
            *(uint32_t*)(ds + (size_t)p*A_STR + c*2) = pack2h(y0, y1);
        }
        __syncthreads();

        float dS[4][8][4] = {};
        MAINLOOP_R(su)

        float rsm[4][2] = {}, rqm[4][2] = {};
        #pragma unroll
        for (int s = 0; s < 4; s++) {
            #pragma unroll
            for (int f = 0; f < 8; f++) {
                int c = nb + f*8 + q2;
                float bb0 = b2s[c], bb1 = b2s[c+1], v;
                v = dS[s][f][0]+bb0; rsm[s][0]+=v; rqm[s][0]+=v*v;
                v = dS[s][f][1]+bb1; rsm[s][0]+=v; rqm[s][0]+=v*v;
                v = dS[s][f][2]+bb0; rsm[s][1]+=v; rqm[s][1]+=v*v;
                v = dS[s][f][3]+bb1; rsm[s][1]+=v; rqm[s][1]+=v*v;
            }
        }
        #pragma unroll
        for (int s = 0; s < 4; s++) {
            #pragma unroll
            for (int h = 0; h < 2; h++) {
                rsm[s][h] += __shfl_xor_sync(~0u, rsm[s][h], 1);
                rsm[s][h] += __shfl_xor_sync(~0u, rsm[s][h], 2);
                rqm[s][h] += __shfl_xor_sync(~0u, rqm[s][h], 1);
                rqm[s][h] += __shfl_xor_sync(~0u, rqm[s][h], 2);
            }
        }
        if ((lane & 3) == 0) {
            int w4 = wid & 3;
            #pragma unroll
            for (int s = 0; s < 4; s++) {
                #pragma unroll
                for (int h = 0; h < 2; h++) {
                    int row = mt0 + s*32 + h*8 + r;
                    srS[row][w4] = rsm[s][h];
                    srQ[row][w4] = rqm[s][h];
                }
            }
        }
        __syncthreads();
        if (tid < TM_) {
            float Ss = srS[tid][0]+srS[tid][1]+srS[tid][2]+srS[tid][3];
            float Qs = srQ[tid][0]+srQ[tid][1]+srQ[tid][2]+srQ[tid][3];
            float mn = Ss * (1.f/CP_);
            sMean[tid] = mn;
            sRstd[tid] = rsqrtf(Qs*(1.f/CP_) - mn*mn + 1e-5f);
        }
        __syncthreads();

        {
            unsigned char* lw = d_localA + (size_t)tile*A_IMG;
            float cm[16];
            #pragma unroll
            for (int i = 0; i < 16; i++) cm[i] = -FLT_MAX;
            #pragma unroll
            for (int s = 0; s < 4; s++) {
                int row0 = mt0 + s*32 + r, row1 = row0 + 8;
                float m0 = sMean[row0], rr0 = sRstd[row0];
                float m1 = sMean[row1], rr1 = sRstd[row1];
                #pragma unroll
                for (int f = 0; f < 8; f++) {
                    int c = nb + f*8 + q2;
                    float bb0=b2s[c], bb1=b2s[c+1], g0=g2s[c], g1=g2s[c+1];
                    float e0=e2s[c], e1=e2s[c+1];
                    float v00 = (dS[s][f][0]+bb0-m0)*rr0*g0+e0;
                    float v01 = (dS[s][f][1]+bb1-m0)*rr0*g1+e1;
                    float v10 = (dS[s][f][2]+bb0-m1)*rr1*g0+e0;
                    float v11 = (dS[s][f][3]+bb1-m1)*rr1*g1+e1;
                    *(uint32_t*)(lw + (size_t)row0*A_STR + c*2) = pack2h(v00, v01);
                    *(uint32_t*)(lw + (size_t)row1*A_STR + c*2) = pack2h(v10, v11);
                    cm[2*f]   = fmaxf(cm[2*f],   fmaxf(v00, v10));
                    cm[2*f+1] = fmaxf(cm[2*f+1], fmaxf(v01, v11));
                }
            }
            #pragma unroll
            for (int i = 0; i < 16; i++) {
                cm[i] = fmaxf(cm[i], __shfl_xor_sync(~0u, cm[i], 4));
                cm[i] = fmaxf(cm[i], __shfl_xor_sync(~0u, cm[i], 8));
                cm[i] = fmaxf(cm[i], __shfl_xor_sync(~0u, cm[i], 16));
            }
            if ((lane >> 2) == 0) {
                int grp = wid >> 2;
                #pragma unroll
                for (int f = 0; f < 8; f++) {
                    int c = nb + f*8 + q2;
                    scx[grp][c]   = cm[2*f];
                    scx[grp][c+1] = cm[2*f+1];
                }
            }
        }
        __syncthreads();
        atomicMaxFloat(&d_gmax[bv*CP_ + tid], fmaxf(scx[0][tid], scx[1][tid]));
        __syncthreads();
    }
}

// ---- kG2 (persistent, M=128): local -> GEMM(W3top resident) -> z -----------
__global__ void __launch_bounds__(256) kG2() {
    extern __shared__ unsigned char ds[];
    int tid = threadIdx.x, lane = tid & 31, wid = tid >> 5;
    uint32_t su = sm2u(ds);

    loadResidentB(su, d_W3f, tid); CPCOMMIT();
    CPWAIT0();
    __syncthreads();

    int mt0 = (wid >> 2) * 16;
    int nb  = (wid & 3) * 64;
    uint32_t aoff0 = (uint32_t)(mt0 + (lane&7) + ((lane>>3)&1)*8)*A_STR + (lane>>4)*16;
    uint32_t boff  = (uint32_t)(nb + (lane&7) + (lane>>4)*8)*A_STR + ((lane>>3)&1)*16;
    int r = lane >> 2, q2 = (lane & 3)*2;

    for (int tile = blockIdx.x; tile < NT_; tile += GRIDP) {
        {
            const unsigned char* src = d_localA + (size_t)tile*A_IMG;
            for (int i = tid; i < A_IMG/16; i += 256)
                CPA16(su + (uint32_t)i*16, src + (size_t)i*16);
        }
        CPCOMMIT();
        CPWAIT0();
        __syncthreads();

        float dS[4][8][4] = {};
        MAINLOOP_R(su)
        __syncthreads();   // all reads done before next iteration's cp.async

        uint32_t* zb = d_z + (size_t)tile*TM_*128;
        #pragma unroll
        for (int s = 0; s < 4; s++) {
            int row0 = mt0 + s*32 + r, row1 = row0 + 8;
            #pragma unroll
            for (int f = 0; f < 8; f++) {
                int cw = (nb + f*8 + q2) >> 1;
                zb[(size_t)row0*128 + cw] = pack2h(dS[s][f][0], dS[s][f][1]);
                zb[(size_t)row1*128 + cw] = pack2h(dS[s][f][2], dS[s][f][3]);
            }
        }
    }
}

// ---------------- kC: gpart = global_xyz @ W3[256:512] + b3 -----------------
__global__ void __launch_bounds__(256) kC(const float* __restrict__ W3,
                                          const float* __restrict__ b3) {
    int bv = blockIdx.x;
    int c  = threadIdx.x;
    __shared__ float sg[CP_];
    __shared__ float ws[32*CP_];
    sg[c] = d_gmax[bv*CP_ + c];
    float acc = b3[c];
    for (int ko = 0; ko < 8; ko++) {
        __syncthreads();
        const float4* src = (const float4*)(W3 + (size_t)(256 + ko*32)*CP_);
        for (int i = c; i < 32*CP_/4; i += 256) ((float4*)ws)[i] = src[i];
        __syncthreads();
        #pragma unroll 8
        for (int kk = 0; kk < 32; kk++)
            acc += sg[ko*32+kk] * ws[kk*CP_ + c];
    }
    d_gpart[bv*CP_ + c] = acc;
}

// ---------------- kD: streaming LN3 + ReLU + W4 -> weights ------------------
__global__ void __launch_bounds__(256) kD(const float* __restrict__ masks,
    const float* __restrict__ g3, const float* __restrict__ be3,
    const float* __restrict__ W4)
{
    __shared__ float sGp[CP_], sG3[CP_], sE3[CP_], sW4[CP_];
    int blk = blockIdx.x;
    int bv = blk >> 5;
    int pbase = (blk & 31) * 512;
    int tid = threadIdx.x, lane = tid & 31, wid = tid >> 5;

    sGp[tid] = d_gpart[bv*CP_ + tid];
    sG3[tid] = g3[tid]; sE3[tid] = be3[tid]; sW4[tid] = W4[tid];
    __syncthreads();

    int cbase = lane*8;
    float gp[8], gg[8], ee[8], ww[8];
    #pragma unroll
    for (int j = 0; j < 8; j++) {
        gp[j]=sGp[cbase+j]; gg[j]=sG3[cbase+j]; ee[j]=sE3[cbase+j]; ww[j]=sW4[cbase+j];
    }

    float dacc = 0.f;
    for (int pp = wid; pp < 512; pp += 8) {
        int n = pbase + pp;
        size_t pt = (size_t)bv*N_ + n;
        uint4 w = *(const uint4*)(d_z + pt*128 + lane*4);
        uint32_t ws4[4] = {w.x, w.y, w.z, w.w};
        float v[8];
        #pragma unroll
        for (int j = 0; j < 4; j++) {
            __half2 h2 = *reinterpret_cast<__half2*>(&ws4[j]);
            float2 f = __half22float2(h2);
            v[2*j]   = f.x + gp[2*j];
            v[2*j+1] = f.y + gp[2*j+1];
        }
        float s = 0.f, q = 0.f;
        #pragma unroll
        for (int j = 0; j < 8; j++) { s += v[j]; q += v[j]*v[j]; }
        #pragma unroll
        for (int o = 16; o > 0; o >>= 1) {
            s += __shfl_xor_sync(~0u, s, o);
            q += __shfl_xor_sync(~0u, q, o);
        }
        float mean = s * (1.f/CP_);
        float rstd = rsqrtf(q*(1.f/CP_) - mean*mean + 1e-5f);
        float dot = 0.f;
        #pragma unroll
        for (int j = 0; j < 8; j++)
            dot += fmaxf((v[j]-mean)*rstd*gg[j] + ee[j], 0.f) * ww[j];
        #pragma unroll
        for (int o = 16; o > 0; o >>= 1) dot += __shfl_xor_sync(~0u, dot, o);
        if (lane == 0) {
            float m = masks[pt];
            float wgt = 2.f * m / (1.f + expf(-dot));
            d_mw[pt] = wgt;
            dacc += wgt;
        }
    }
    if (lane == 0) atomicAdd(&d_denom[bv], dacc);
}

// ---------------- kE: weighted pooling + epilogue ---------------------------
__global__ void __launch_bounds__(256) kE(const float* __restrict__ feats,
                                          float* __restrict__ out) {
    int blk = blockIdx.x;
    int b = blk >> 8;
    int c = blk & 255;
    int tid = threadIdx.x;

    const float* f   = feats + (size_t)(b*CP_ + c)*N_;
    const float* mw0 = d_mw + (size_t)(b*4+0)*N_;
    const float* mw1 = d_mw + (size_t)(b*4+1)*N_;
    const float* mw2 = d_mw + (size_t)(b*4+2)*N_;
    const float* mw3 = d_mw + (size_t)(b*4+3)*N_;

    float a0=0.f, a1=0.f, a2=0.f, a3=0.f;
    for (int n = tid; n < N_; n += 256) {
        float fv = f[n];
        a0 += fv*mw0[n]; a1 += fv*mw1[n]; a2 += fv*mw2[n]; a3 += fv*mw3[n];
    }
    #pragma unroll
    for (int o = 16; o > 0; o >>= 1) {
        a0 += __shfl_xor_sync(0xffffffffu, a0, o);
        a1 += __shfl_xor_sync(0xffffffffu, a1, o);
        a2 += __shfl_xor_sync(0xffffffffu, a2, o);
        a3 += __shfl_xor_sync(0xffffffffu, a3, o);
    }
    __shared__ float sr[4][8];
    int lane = tid & 31, warp = tid >> 5;
    if (lane == 0) { sr[0][warp]=a0; sr[1][warp]=a1; sr[2][warp]=a2; sr[3][warp]=a3; }
    __syncthreads();
    if (tid < 4) {
        float ps = 0.f;
        #pragma unroll
        for (int w = 0; w < 8; w++) ps += sr[tid][w];
        int bvv = b*4 + tid;
        float den = fmaxf(d_denom[bvv], 1e-8f);
        out[(size_t)bvv*CP_ + c] = ps/den + d_gmax[bvv*CP_ + c];
    }
}

// ---------------- launch ----------------------------------------------------
extern "C" void kernel_launch(void* const* d_in, const int* in_sizes, int n_in,
                              void* d_out, int out_size) {
    const float* xyz = (const float*)d_in[0];
    const float* pf  = (const float*)d_in[1];
    const float* pm  = (const float*)d_in[2];
    const float* W1  = (const float*)d_in[3];
    const float* b1  = (const float*)d_in[4];
    const float* g1  = (const float*)d_in[5];
    const float* be1 = (const float*)d_in[6];
    const float* W2  = (const float*)d_in[7];
    const float* b2  = (const float*)d_in[8];
    const float* g2  = (const float*)d_in[9];
    const float* be2 = (const float*)d_in[10];
    const float* W3  = (const float*)d_in[11];
    const float* b3  = (const float*)d_in[12];
    const float* g3  = (const float*)d_in[13];
    const float* be3 = (const float*)d_in[14];
    const float* W4  = (const float*)d_in[15];
    float* out = (float*)d_out;

    static int configured = 0;
    if (!configured) {
        cudaFuncSetAttribute(kG1, cudaFuncAttributeMaxDynamicSharedMemorySize, DYN_SMEM);
        cudaFuncSetAttribute(kG2, cudaFuncAttributeMaxDynamicSharedMemorySize, DYN_SMEM);
        configured = 1;
    }

    kPre<<<514, 256>>>(W2, W3, W1, b1, xyz, pm);
    kG1<<<GRIDP, 256, DYN_SMEM>>>(xyz, W1, b1, g1, be1, b2, g2, be2);
    kC<<<BV_, 256>>>(W3, b3);
    kG2<<<GRIDP, 256, DYN_SMEM>>>();
    kD<<<1024, 256>>>(pm, g3, be3, W4);
    kE<<<B_*CP_, 256>>>(pf, out);
}